// round 12
// baseline (speedup 1.0000x reference)
#include <cuda_runtime.h>
#include <cuda_fp16.h>

#define HID 128
#define NMAX 20000
#define EMAX 640000

// ---- scratch (__device__ globals; allocation-free rule) ----
// g_cnt: zero at module load; scan re-zeros after reading (self-cleaning).
__device__ int    g_is64;
__device__ __align__(16) int g_cnt[NMAX];
__device__ __align__(16) int g_prefix[NMAX + 4];
__device__ int    g_rank[EMAX];
__device__ int    g_srcs[EMAX];
__device__ __half g_feat16[NMAX * HID];   // fp16 features (gather input)

// ---------------------------------------------------------------------------
// Kernel 1: dtype probe (sync-at-top for cross-replay PDL safety).
// ---------------------------------------------------------------------------
__global__ void detect_kernel(const unsigned* __restrict__ w, int m) {
    cudaGridDependencySynchronize();
    int bad = 0;
    for (int j = threadIdx.x; j < m; j += blockDim.x)
        if (w[2 * j + 1] != 0u) bad = 1;
    bad = __syncthreads_or(bad);
    if (threadIdx.x == 0) g_is64 = bad ? 0 : 1;
}

// ---------------------------------------------------------------------------
// Kernel 2: PRE-SYNC: fp16 conversion (inputs only, value-idempotent).
// POST-SYNC: histogram + rank.
// ---------------------------------------------------------------------------
__global__ void __launch_bounds__(256) hist_conv_kernel(
    const void* __restrict__ ei, int E,
    const float* __restrict__ feat, int tot4)
{
    int gtid = blockIdx.x * blockDim.x + threadIdx.x;
    int gstride = gridDim.x * blockDim.x;

    const float4* f4 = (const float4*)feat;
    uint2* h4 = (uint2*)g_feat16;
    for (int k = gtid; k < tot4; k += gstride) {
        float4 v = f4[k];
        __half2 h0 = __floats2half2_rn(v.x, v.y);
        __half2 h1 = __floats2half2_rn(v.z, v.w);
        uint2 o;
        o.x = *(unsigned*)&h0;
        o.y = *(unsigned*)&h1;
        h4[k] = o;
    }

    cudaGridDependencySynchronize();

    int base = gtid * 2;
    if (base >= E) return;
    int m = min(2, E - base);
    int d[2];
    if (g_is64) {
        const long long* p = (const long long*)ei + E;
#pragma unroll
        for (int i = 0; i < 2; i++) if (i < m) d[i] = (int)p[base + i];
    } else {
        const int* p = (const int*)ei + E;
#pragma unroll
        for (int i = 0; i < 2; i++) if (i < m) d[i] = p[base + i];
    }
    int r[2];
#pragma unroll
    for (int i = 0; i < 2; i++) if (i < m) r[i] = atomicAdd(&g_cnt[d[i]], 1);
#pragma unroll
    for (int i = 0; i < 2; i++) if (i < m) g_rank[base + i] = r[i];
}

// ---------------------------------------------------------------------------
// Kernel 3: single-block scan (register-cached, int4); re-zeros g_cnt.
// ---------------------------------------------------------------------------
#define SCH 20

__global__ void __launch_bounds__(1024) scan_kernel(int n) {
    cudaGridDependencySynchronize();
    __shared__ int warp_sums[32];
    int t = threadIdx.x;
    int lane = t & 31, wid = t >> 5;
    int beg = t * SCH;

    int c[SCH];
    int s = 0;
    bool full = (beg + SCH <= n);
    if (full) {
        const int4* p = (const int4*)(g_cnt + beg);
#pragma unroll
        for (int q = 0; q < SCH / 4; q++) {
            int4 v = p[q];
            c[q * 4 + 0] = v.x; c[q * 4 + 1] = v.y;
            c[q * 4 + 2] = v.z; c[q * 4 + 3] = v.w;
            s += v.x + v.y + v.z + v.w;
        }
        int4 z = make_int4(0, 0, 0, 0);
        int4* pz = (int4*)(g_cnt + beg);
#pragma unroll
        for (int q = 0; q < SCH / 4; q++) pz[q] = z;
    } else {
#pragma unroll
        for (int q = 0; q < SCH; q++) {
            int idx = beg + q;
            c[q] = (idx < n) ? g_cnt[idx] : 0;
            if (idx < n) g_cnt[idx] = 0;
            s += c[q];
        }
    }

    int v = s;
#pragma unroll
    for (int o = 1; o < 32; o <<= 1) {
        int u = __shfl_up_sync(0xffffffffu, v, o);
        if (lane >= o) v += u;
    }
    if (lane == 31) warp_sums[wid] = v;
    __syncthreads();
    if (wid == 0) {
        int w = warp_sums[lane];
#pragma unroll
        for (int o = 1; o < 32; o <<= 1) {
            int u = __shfl_up_sync(0xffffffffu, w, o);
            if (lane >= o) w += u;
        }
        warp_sums[lane] = w;
    }
    __syncthreads();

    int run = v - s + (wid > 0 ? warp_sums[wid - 1] : 0);
    int pre[SCH];
#pragma unroll
    for (int q = 0; q < SCH; q++) { pre[q] = run; run += c[q]; }

    if (full) {
        int4* p = (int4*)(g_prefix + beg);
#pragma unroll
        for (int q = 0; q < SCH / 4; q++)
            p[q] = make_int4(pre[q * 4 + 0], pre[q * 4 + 1],
                             pre[q * 4 + 2], pre[q * 4 + 3]);
    } else {
#pragma unroll
        for (int q = 0; q < SCH; q++)
            if (beg + q < n) g_prefix[beg + q] = pre[q];
    }
    if (t == 0) g_prefix[n] = warp_sums[31];
}

// ---------------------------------------------------------------------------
// Kernel 4: PRE-SYNC: coalesced edge loads. POST-SYNC: scatter.
// ---------------------------------------------------------------------------
__global__ void __launch_bounds__(256) place_kernel(const void* __restrict__ ei, int E) {
    int base = (blockIdx.x * blockDim.x + threadIdx.x) * 2;
    int m = (base < E) ? min(2, E - base) : 0;
    int s[2], d[2];
    if (m) {
        if (g_is64) {
            const long long* p = (const long long*)ei;
#pragma unroll
            for (int i = 0; i < 2; i++) if (i < m) { s[i] = (int)p[base + i]; d[i] = (int)p[E + base + i]; }
        } else {
            const int* p = (const int*)ei;
#pragma unroll
            for (int i = 0; i < 2; i++) if (i < m) { s[i] = p[base + i]; d[i] = p[E + base + i]; }
        }
    }
    cudaGridDependencySynchronize();
    if (!m) return;
    int r[2], pf[2];
#pragma unroll
    for (int i = 0; i < 2; i++) if (i < m) r[i] = g_rank[base + i];
#pragma unroll
    for (int i = 0; i < 2; i++) if (i < m) pf[i] = g_prefix[d[i]];
#pragma unroll
    for (int i = 0; i < 2; i++) if (i < m) g_srcs[pf[i] + r[i]] = s[i];
}

// ---------------------------------------------------------------------------
// Kernel 5 (FUSED agg + GEMM): out = mean_agg @ Wl^T + feat @ Wr^T + bl
// Per block (64 rows): PRE-SYNC feat@Wr chunks 8..15 -> sync -> warp-level
// gather/aggregate into persistent tf32 smem tile (pre-swizzled) ->
// agg@Wl chunks 0..7 reading A straight from that tile.
// ---------------------------------------------------------------------------
#define BM 64
#define BK 16
#define SW(r, c) ((r) * BK + ((c) ^ ((((r) >> 1) & 3) << 2)))

__device__ __forceinline__ unsigned f2tf32(float x) {
    unsigned r;
    asm("cvt.rna.tf32.f32 %0, %1;" : "=r"(r) : "f"(x));
    return r;
}

__device__ __forceinline__ void mma_tf32(float* c, const unsigned* a, const unsigned* b) {
    asm volatile(
        "mma.sync.aligned.m16n8k8.row.col.f32.tf32.tf32.f32 "
        "{%0,%1,%2,%3},{%4,%5,%6,%7},{%8,%9},{%0,%1,%2,%3};"
        : "+f"(c[0]), "+f"(c[1]), "+f"(c[2]), "+f"(c[3])
        : "r"(a[0]), "r"(a[1]), "r"(a[2]), "r"(a[3]), "r"(b[0]), "r"(b[1]));
}

__global__ void __launch_bounds__(256) agg_gemm_tc(
    const float* __restrict__ feat,
    const float* __restrict__ Wl,
    const float* __restrict__ bl,
    const float* __restrict__ Wr,
    float* __restrict__ out,
    int n)
{
    __shared__ unsigned sAgg[8][BM * BK + 4];  // persistent tf32 agg tile, SW layout
    __shared__ unsigned sA[2][BM * BK];
    __shared__ unsigned sB[2][128 * BK];

    int tid = threadIdx.x;
    int wid = tid >> 5, lane = tid & 31;
    int wm = wid & 1;
    int wn = wid >> 1;
    int g = lane >> 2;
    int tg = lane & 3;
    int row0 = blockIdx.x * BM;

    float acc[2][4][4];
#pragma unroll
    for (int mt = 0; mt < 2; mt++)
#pragma unroll
        for (int nt = 0; nt < 4; nt++)
#pragma unroll
            for (int q = 0; q < 4; q++) acc[mt][nt][q] = 0.f;

    uint4 rga, rgb[2];

    int a_r = tid >> 2;
    int a_c4 = (tid & 3) * 4;

    auto ldgA_feat = [&](int ck) {
        int k0 = (ck & 7) * BK;
        int gr = row0 + a_r;
        float4 v = make_float4(0.f, 0.f, 0.f, 0.f);
        if (gr < n) v = *(const float4*)(feat + (size_t)gr * HID + k0 + a_c4);
        rga = make_uint4(f2tf32(v.x), f2tf32(v.y), f2tf32(v.z), f2tf32(v.w));
    };
    auto ldgB = [&](const float* W, int ck) {
        int k0 = (ck & 7) * BK;
#pragma unroll
        for (int q = 0; q < 2; q++) {
            int idx = q * 256 + tid;
            int br = idx >> 2;
            int bc4 = (idx & 3) * 4;
            float4 w = *(const float4*)(W + (size_t)br * HID + k0 + bc4);
            rgb[q] = make_uint4(f2tf32(w.x), f2tf32(w.y), f2tf32(w.z), f2tf32(w.w));
        }
    };
    auto stsA = [&](int b) {
        *(uint4*)&sA[b][SW(a_r, a_c4)] = rga;
    };
    auto stsB = [&](int b) {
#pragma unroll
        for (int q = 0; q < 2; q++) {
            int idx = q * 256 + tid;
            int br = idx >> 2;
            int bc4 = (idx & 3) * 4;
            *(uint4*)&sB[b][SW(br, bc4)] = rgb[q];
        }
    };
    auto mma_block = [&](const unsigned* Asrc, const unsigned* Bsrc) {
#pragma unroll
        for (int kk = 0; kk < 2; kk++) {
            int ko = kk * 8;
            unsigned af[2][4], bf[4][2];
#pragma unroll
            for (int mt = 0; mt < 2; mt++) {
                int rb_ = wm * 32 + mt * 16;
                af[mt][0] = Asrc[SW(rb_ + g,     ko + tg)];
                af[mt][1] = Asrc[SW(rb_ + g + 8, ko + tg)];
                af[mt][2] = Asrc[SW(rb_ + g,     ko + tg + 4)];
                af[mt][3] = Asrc[SW(rb_ + g + 8, ko + tg + 4)];
            }
#pragma unroll
            for (int nt = 0; nt < 4; nt++) {
                int cb = wn * 32 + nt * 8;
                bf[nt][0] = Bsrc[SW(cb + g, ko + tg)];
                bf[nt][1] = Bsrc[SW(cb + g, ko + tg + 4)];
            }
#pragma unroll
            for (int mt = 0; mt < 2; mt++)
#pragma unroll
                for (int nt = 0; nt < 4; nt++)
                    mma_tf32(acc[mt][nt], af[mt], bf[nt]);
        }
    };

    // ---- Phase A (pre-sync): feat @ Wr, chunks 8..15 ----
    ldgA_feat(8); ldgB(Wr, 8);
    stsA(0); stsB(0);
    __syncthreads();
    for (int i = 0; i < 8; i++) {
        if (i < 7) { ldgA_feat(9 + i); ldgB(Wr, 9 + i); }
        mma_block(sA[i & 1], sB[i & 1]);
        if (i < 7) {
            stsA((i + 1) & 1); stsB((i + 1) & 1);
            __syncthreads();
        }
    }

    // ---- Phase B (post-sync): aggregate 64 nodes into sAgg ----
    cudaGridDependencySynchronize();
    ldgB(Wl, 0);            // independent of agg; issue before gather
    stsB(0);

    const uint2* f16 = (const uint2*)g_feat16;
    int ckw = lane >> 2;            // this lane's chunk (cols lane*4..+3)
    int c4w = (lane & 3) * 4;
#pragma unroll 1
    for (int j = 0; j < 8; j++) {
        int rl = wid * 8 + j;
        int node = row0 + rl;
        int beg = 0, end = 0;
        if (node < n) { beg = g_prefix[node]; end = g_prefix[node + 1]; }

        float4 a0 = make_float4(0.f, 0.f, 0.f, 0.f);
        float4 a1 = a0, a2 = a0, a3 = a0;
        auto addv = [](float4& a, uint2 v) {
            __half2 h0 = *(__half2*)&v.x;
            __half2 h1 = *(__half2*)&v.y;
            float2 f0 = __half22float2(h0);
            float2 f1 = __half22float2(h1);
            a.x += f0.x; a.y += f0.y; a.z += f1.x; a.w += f1.y;
        };
        int e = beg;
        for (; e + 4 <= end; e += 4) {
            int s0 = g_srcs[e + 0], s1 = g_srcs[e + 1];
            int s2 = g_srcs[e + 2], s3 = g_srcs[e + 3];
            uint2 v0 = f16[(size_t)s0 * 32 + lane];
            uint2 v1 = f16[(size_t)s1 * 32 + lane];
            uint2 v2 = f16[(size_t)s2 * 32 + lane];
            uint2 v3 = f16[(size_t)s3 * 32 + lane];
            addv(a0, v0); addv(a1, v1); addv(a2, v2); addv(a3, v3);
        }
        for (; e < end; e++) {
            uint2 v = f16[(size_t)g_srcs[e] * 32 + lane];
            addv(a0, v);
        }
        float inv = (end > beg) ? 1.f / (float)(end - beg) : 0.f;
        float sx = (a0.x + a1.x + a2.x + a3.x) * inv;
        float sy = (a0.y + a1.y + a2.y + a3.y) * inv;
        float sz = (a0.z + a1.z + a2.z + a3.z) * inv;
        float sw = (a0.w + a1.w + a2.w + a3.w) * inv;
        *(uint4*)&sAgg[ckw][SW(rl, c4w)] =
            make_uint4(f2tf32(sx), f2tf32(sy), f2tf32(sz), f2tf32(sw));
    }
    __syncthreads();

    // ---- Phase C: agg @ Wl, chunks 0..7 (A direct from sAgg) ----
    for (int i = 0; i < 8; i++) {
        if (i < 7) ldgB(Wl, i + 1);
        mma_block(sAgg[i], sB[i & 1]);
        if (i < 7) {
            stsB((i + 1) & 1);
            __syncthreads();
        }
    }

    // ---- epilogue ----
#pragma unroll
    for (int nt = 0; nt < 4; nt++) {
        int c = wn * 32 + nt * 8 + tg * 2;
        float b0 = bl[c], b1 = bl[c + 1];
#pragma unroll
        for (int mt = 0; mt < 2; mt++) {
            int r = row0 + wm * 32 + mt * 16 + g;
            if (r < n) {
                float2 o = make_float2(acc[mt][nt][0] + b0, acc[mt][nt][1] + b1);
                *(float2*)(out + (size_t)r * HID + c) = o;
            }
            if (r + 8 < n) {
                float2 o = make_float2(acc[mt][nt][2] + b0, acc[mt][nt][3] + b1);
                *(float2*)(out + (size_t)(r + 8) * HID + c) = o;
            }
        }
    }
}

// ---------------------------------------------------------------------------
// PDL launch helper.
// ---------------------------------------------------------------------------
template <typename K, typename... Args>
static inline void launch_pdl(K kernel, dim3 grid, dim3 block, Args... args) {
    cudaLaunchConfig_t cfg = {};
    cfg.gridDim = grid;
    cfg.blockDim = block;
    cfg.dynamicSmemBytes = 0;
    cfg.stream = 0;
    cudaLaunchAttribute attr[1];
    attr[0].id = cudaLaunchAttributeProgrammaticStreamSerialization;
    attr[0].val.programmaticStreamSerializationAllowed = 1;
    cfg.attrs = attr;
    cfg.numAttrs = 1;
    cudaLaunchKernelEx(&cfg, kernel, args...);
}

// ---------------------------------------------------------------------------
extern "C" void kernel_launch(void* const* d_in, const int* in_sizes, int n_in,
                              void* d_out, int out_size)
{
    const float* feat = (const float*)d_in[0];
    const void*  ei   = d_in[1];
    const float* Wl   = (const float*)d_in[2];
    const float* bl   = (const float*)d_in[3];
    const float* Wr   = (const float*)d_in[4];
    float* out = (float*)d_out;

    int n = in_sizes[0] / HID;          // 20000
    int E = in_sizes[1] / 2;            // 640000
    int tot4 = n * HID / 4;

    int n_check = E < 4096 ? E : 4096;
    int eb2 = (E / 2 + 255) / 256;

    launch_pdl(detect_kernel, dim3(1), dim3(256), (const unsigned*)ei, n_check);
    launch_pdl(hist_conv_kernel, dim3(eb2), dim3(256), ei, E, feat, tot4);
    launch_pdl(scan_kernel, dim3(1), dim3(1024), n);
    launch_pdl(place_kernel, dim3(eb2), dim3(256), ei, E);
    launch_pdl(agg_gemm_tc, dim3((n + BM - 1) / BM), dim3(256),
               feat, Wl, bl, Wr, out, n);
}

// round 13
// speedup vs baseline: 1.2288x; 1.2288x over previous
#include <cuda_runtime.h>
#include <cuda_fp16.h>

#define HID 128
#define NMAX 20000
#define EMAX 640000

// ---- scratch (__device__ globals; allocation-free rule) ----
// g_cnt: zero at module load; scan re-zeros after reading (self-cleaning).
__device__ __align__(16) int g_cnt[NMAX];
__device__ __align__(16) int g_prefix[NMAX + 4];
__device__ int    g_rank[EMAX];
__device__ int    g_srcs[EMAX];
__device__ __half g_feat16[NMAX * HID];   // fp16 features (gather input)
__device__ __half g_agg16[NMAX * HID];    // fp16 aggregated means

// ---------------------------------------------------------------------------
// Local dtype probe: int64 node indices (<2^31) have all-zero high words.
// 8 broadcast loads; P(int32 array fooling this) ~ (5e-5)^8 ~ 0.
// Uniform across threads -> no divergence.
// ---------------------------------------------------------------------------
__device__ __forceinline__ int probe_is64(const unsigned* __restrict__ w) {
    int bad = 0;
#pragma unroll
    for (int i = 0; i < 8; i++) bad |= (w[2 * i + 1] != 0u);
    return !bad;
}

// ---------------------------------------------------------------------------
// Kernel 1: PRE-SYNC: fp16 conversion (inputs only; value-idempotent, so
// safe to overlap the previous replay's tail). POST-SYNC: histogram + rank.
// ---------------------------------------------------------------------------
__global__ void __launch_bounds__(256) hist_conv_kernel(
    const void* __restrict__ ei, int E,
    const float* __restrict__ feat, int tot4)
{
    int gtid = blockIdx.x * blockDim.x + threadIdx.x;
    int gstride = gridDim.x * blockDim.x;

    const float4* f4 = (const float4*)feat;
    uint2* h4 = (uint2*)g_feat16;
    for (int k = gtid; k < tot4; k += gstride) {
        float4 v = f4[k];
        __half2 h0 = __floats2half2_rn(v.x, v.y);
        __half2 h1 = __floats2half2_rn(v.z, v.w);
        uint2 o;
        o.x = *(unsigned*)&h0;
        o.y = *(unsigned*)&h1;
        h4[k] = o;
    }

    int is64 = probe_is64((const unsigned*)ei);

    // load dsts pre-sync (reads inputs only)
    int base = gtid * 2;
    int m = (base < E) ? min(2, E - base) : 0;
    int d[2];
    if (m) {
        if (is64) {
            const long long* p = (const long long*)ei + E;
#pragma unroll
            for (int i = 0; i < 2; i++) if (i < m) d[i] = (int)p[base + i];
        } else {
            const int* p = (const int*)ei + E;
#pragma unroll
            for (int i = 0; i < 2; i++) if (i < m) d[i] = p[base + i];
        }
    }

    cudaGridDependencySynchronize();   // g_cnt zeroed by prev replay's scan

    if (!m) return;
    int r[2];
#pragma unroll
    for (int i = 0; i < 2; i++) if (i < m) r[i] = atomicAdd(&g_cnt[d[i]], 1);
#pragma unroll
    for (int i = 0; i < 2; i++) if (i < m) g_rank[base + i] = r[i];
}

// ---------------------------------------------------------------------------
// Kernel 2: single-block scan (register-cached, int4); re-zeros g_cnt.
// ---------------------------------------------------------------------------
#define SCH 20

__global__ void __launch_bounds__(1024) scan_kernel(int n) {
    cudaGridDependencySynchronize();
    __shared__ int warp_sums[32];
    int t = threadIdx.x;
    int lane = t & 31, wid = t >> 5;
    int beg = t * SCH;

    int c[SCH];
    int s = 0;
    bool full = (beg + SCH <= n);
    if (full) {
        const int4* p = (const int4*)(g_cnt + beg);
#pragma unroll
        for (int q = 0; q < SCH / 4; q++) {
            int4 v = p[q];
            c[q * 4 + 0] = v.x; c[q * 4 + 1] = v.y;
            c[q * 4 + 2] = v.z; c[q * 4 + 3] = v.w;
            s += v.x + v.y + v.z + v.w;
        }
        int4 z = make_int4(0, 0, 0, 0);
        int4* pz = (int4*)(g_cnt + beg);
#pragma unroll
        for (int q = 0; q < SCH / 4; q++) pz[q] = z;
    } else {
#pragma unroll
        for (int q = 0; q < SCH; q++) {
            int idx = beg + q;
            c[q] = (idx < n) ? g_cnt[idx] : 0;
            if (idx < n) g_cnt[idx] = 0;
            s += c[q];
        }
    }

    int v = s;
#pragma unroll
    for (int o = 1; o < 32; o <<= 1) {
        int u = __shfl_up_sync(0xffffffffu, v, o);
        if (lane >= o) v += u;
    }
    if (lane == 31) warp_sums[wid] = v;
    __syncthreads();
    if (wid == 0) {
        int w = warp_sums[lane];
#pragma unroll
        for (int o = 1; o < 32; o <<= 1) {
            int u = __shfl_up_sync(0xffffffffu, w, o);
            if (lane >= o) w += u;
        }
        warp_sums[lane] = w;
    }
    __syncthreads();

    int run = v - s + (wid > 0 ? warp_sums[wid - 1] : 0);
    int pre[SCH];
#pragma unroll
    for (int q = 0; q < SCH; q++) { pre[q] = run; run += c[q]; }

    if (full) {
        int4* p = (int4*)(g_prefix + beg);
#pragma unroll
        for (int q = 0; q < SCH / 4; q++)
            p[q] = make_int4(pre[q * 4 + 0], pre[q * 4 + 1],
                             pre[q * 4 + 2], pre[q * 4 + 3]);
    } else {
#pragma unroll
        for (int q = 0; q < SCH; q++)
            if (beg + q < n) g_prefix[beg + q] = pre[q];
    }
    if (t == 0) g_prefix[n] = warp_sums[31];
}

// ---------------------------------------------------------------------------
// Kernel 3: PRE-SYNC: coalesced edge loads (inputs only).
// POST-SYNC: rank/prefix reads + scatter store.
// ---------------------------------------------------------------------------
__global__ void __launch_bounds__(256) place_kernel(const void* __restrict__ ei, int E) {
    int is64 = probe_is64((const unsigned*)ei);
    int base = (blockIdx.x * blockDim.x + threadIdx.x) * 2;
    int m = (base < E) ? min(2, E - base) : 0;
    int s[2], d[2];
    if (m) {
        if (is64) {
            const long long* p = (const long long*)ei;
#pragma unroll
            for (int i = 0; i < 2; i++) if (i < m) { s[i] = (int)p[base + i]; d[i] = (int)p[E + base + i]; }
        } else {
            const int* p = (const int*)ei;
#pragma unroll
            for (int i = 0; i < 2; i++) if (i < m) { s[i] = p[base + i]; d[i] = p[E + base + i]; }
        }
    }
    cudaGridDependencySynchronize();
    if (!m) return;
    int r[2], pf[2];
#pragma unroll
    for (int i = 0; i < 2; i++) if (i < m) r[i] = g_rank[base + i];
#pragma unroll
    for (int i = 0; i < 2; i++) if (i < m) pf[i] = g_prefix[d[i]];
#pragma unroll
    for (int i = 0; i < 2; i++) if (i < m) g_srcs[pf[i] + r[i]] = s[i];
}

// ---------------------------------------------------------------------------
// Kernel 4: one warp per dst node: gather-sum fp16 features, fp32 acc,
// fp16 mean out. High-occupancy standalone kernel (LTS-bandwidth-bound).
// ---------------------------------------------------------------------------
__global__ void __launch_bounds__(256) agg_kernel(int n) {
    cudaGridDependencySynchronize();
    int node = (blockIdx.x * blockDim.x + threadIdx.x) >> 5;
    int lane = threadIdx.x & 31;
    if (node >= n) return;
    int beg = g_prefix[node], end = g_prefix[node + 1];

    const uint2* f16 = (const uint2*)g_feat16;

    float4 a0 = make_float4(0.f, 0.f, 0.f, 0.f);
    float4 a1 = a0, a2 = a0, a3 = a0;

    auto addv = [](float4& a, uint2 v) {
        __half2 h0 = *(__half2*)&v.x;
        __half2 h1 = *(__half2*)&v.y;
        float2 f0 = __half22float2(h0);
        float2 f1 = __half22float2(h1);
        a.x += f0.x; a.y += f0.y; a.z += f1.x; a.w += f1.y;
    };

    int e = beg;
    for (; e + 4 <= end; e += 4) {
        int s0 = g_srcs[e + 0], s1 = g_srcs[e + 1];
        int s2 = g_srcs[e + 2], s3 = g_srcs[e + 3];
        uint2 v0 = f16[(size_t)s0 * 32 + lane];
        uint2 v1 = f16[(size_t)s1 * 32 + lane];
        uint2 v2 = f16[(size_t)s2 * 32 + lane];
        uint2 v3 = f16[(size_t)s3 * 32 + lane];
        addv(a0, v0); addv(a1, v1); addv(a2, v2); addv(a3, v3);
    }
    for (; e < end; e++) {
        uint2 v = f16[(size_t)g_srcs[e] * 32 + lane];
        addv(a0, v);
    }
    float inv = (end > beg) ? 1.f / (float)(end - beg) : 0.f;
    float sx = (a0.x + a1.x + a2.x + a3.x) * inv;
    float sy = (a0.y + a1.y + a2.y + a3.y) * inv;
    float sz = (a0.z + a1.z + a2.z + a3.z) * inv;
    float sw = (a0.w + a1.w + a2.w + a3.w) * inv;
    __half2 o0 = __floats2half2_rn(sx, sy);
    __half2 o1 = __floats2half2_rn(sz, sw);
    uint2 st;
    st.x = *(unsigned*)&o0;
    st.y = *(unsigned*)&o1;
    ((uint2*)g_agg16)[(size_t)node * 32 + lane] = st;
}

// ---------------------------------------------------------------------------
// Kernel 5: TF32 GEMM. PRE-SYNC: feat@Wr chunks 8..15 (inputs only) overlap
// agg; POST-SYNC: agg16@Wl chunks 0..7.
// ---------------------------------------------------------------------------
#define BM 64
#define BK 16
#define SW(r, c) ((r) * BK + ((c) ^ ((((r) >> 1) & 3) << 2)))

__device__ __forceinline__ unsigned f2tf32(float x) {
    unsigned r;
    asm("cvt.rna.tf32.f32 %0, %1;" : "=r"(r) : "f"(x));
    return r;
}

__device__ __forceinline__ void mma_tf32(float* c, const unsigned* a, const unsigned* b) {
    asm volatile(
        "mma.sync.aligned.m16n8k8.row.col.f32.tf32.tf32.f32 "
        "{%0,%1,%2,%3},{%4,%5,%6,%7},{%8,%9},{%0,%1,%2,%3};"
        : "+f"(c[0]), "+f"(c[1]), "+f"(c[2]), "+f"(c[3])
        : "r"(a[0]), "r"(a[1]), "r"(a[2]), "r"(a[3]), "r"(b[0]), "r"(b[1]));
}

__global__ void __launch_bounds__(256) gemm_tc(
    const float* __restrict__ feat,
    const float* __restrict__ Wl,
    const float* __restrict__ bl,
    const float* __restrict__ Wr,
    float* __restrict__ out,
    int n)
{
    __shared__ unsigned sA[2][BM * BK];
    __shared__ unsigned sB[2][128 * BK];

    int tid = threadIdx.x;
    int wid = tid >> 5, lane = tid & 31;
    int wm = wid & 1;
    int wn = wid >> 1;
    int g = lane >> 2;
    int tg = lane & 3;
    int row0 = blockIdx.x * BM;

    float acc[2][4][4];
#pragma unroll
    for (int mt = 0; mt < 2; mt++)
#pragma unroll
        for (int nt = 0; nt < 4; nt++)
#pragma unroll
            for (int q = 0; q < 4; q++) acc[mt][nt][q] = 0.f;

    uint4 rga, rgb[2];

    auto ldg_chunk = [&](int ck) {
        int k0 = (ck & 7) * BK;
        int r = tid >> 2;
        int c4 = (tid & 3) * 4;
        int gr = row0 + r;
        if (ck < 8) {
            float2 f0 = make_float2(0.f, 0.f), f1 = f0;
            if (gr < n) {
                uint2 hv = ((const uint2*)g_agg16)[((size_t)gr * HID + k0 + c4) >> 2];
                f0 = __half22float2(*(__half2*)&hv.x);
                f1 = __half22float2(*(__half2*)&hv.y);
            }
            rga = make_uint4(f2tf32(f0.x), f2tf32(f0.y), f2tf32(f1.x), f2tf32(f1.y));
        } else {
            float4 v = make_float4(0.f, 0.f, 0.f, 0.f);
            if (gr < n) v = *(const float4*)(feat + (size_t)gr * HID + k0 + c4);
            rga = make_uint4(f2tf32(v.x), f2tf32(v.y), f2tf32(v.z), f2tf32(v.w));
        }
        const float* W = (ck < 8) ? Wl : Wr;
#pragma unroll
        for (int q = 0; q < 2; q++) {
            int idx = q * 256 + tid;
            int br = idx >> 2;
            int bc4 = (idx & 3) * 4;
            float4 w = *(const float4*)(W + (size_t)br * HID + k0 + bc4);
            rgb[q] = make_uint4(f2tf32(w.x), f2tf32(w.y), f2tf32(w.z), f2tf32(w.w));
        }
    };

    auto sts_chunk = [&](int b) {
        int r = tid >> 2;
        int c4 = (tid & 3) * 4;
        *(uint4*)&sA[b][SW(r, c4)] = rga;
#pragma unroll
        for (int q = 0; q < 2; q++) {
            int idx = q * 256 + tid;
            int br = idx >> 2;
            int bc4 = (idx & 3) * 4;
            *(uint4*)&sB[b][SW(br, bc4)] = rgb[q];
        }
    };

    // chunk order: 8..15 (feat/Wr, pre-sync) then 0..7 (agg16/Wl, post-sync)
    ldg_chunk(8);
    sts_chunk(0);
    __syncthreads();

    for (int i = 0; i < 16; i++) {
        if (i < 15) {
            int nxt = (i + 9) & 15;
            if (nxt == 0) cudaGridDependencySynchronize();  // before first agg16 load
            ldg_chunk(nxt);
        }
        int b = i & 1;
#pragma unroll
        for (int kk = 0; kk < 2; kk++) {
            int ko = kk * 8;
            unsigned af[2][4], bf[4][2];
#pragma unroll
            for (int mt = 0; mt < 2; mt++) {
                int rb_ = wm * 32 + mt * 16;
                af[mt][0] = sA[b][SW(rb_ + g,     ko + tg)];
                af[mt][1] = sA[b][SW(rb_ + g + 8, ko + tg)];
                af[mt][2] = sA[b][SW(rb_ + g,     ko + tg + 4)];
                af[mt][3] = sA[b][SW(rb_ + g + 8, ko + tg + 4)];
            }
#pragma unroll
            for (int nt = 0; nt < 4; nt++) {
                int cb = wn * 32 + nt * 8;
                bf[nt][0] = sB[b][SW(cb + g, ko + tg)];
                bf[nt][1] = sB[b][SW(cb + g, ko + tg + 4)];
            }
#pragma unroll
            for (int mt = 0; mt < 2; mt++)
#pragma unroll
                for (int nt = 0; nt < 4; nt++)
                    mma_tf32(acc[mt][nt], af[mt], bf[nt]);
        }
        if (i < 15) {
            sts_chunk((i + 1) & 1);
            __syncthreads();
        }
    }

#pragma unroll
    for (int nt = 0; nt < 4; nt++) {
        int c = wn * 32 + nt * 8 + tg * 2;
        float b0 = bl[c], b1 = bl[c + 1];
#pragma unroll
        for (int mt = 0; mt < 2; mt++) {
            int r = row0 + wm * 32 + mt * 16 + g;
            if (r < n) {
                float2 o = make_float2(acc[mt][nt][0] + b0, acc[mt][nt][1] + b1);
                *(float2*)(out + (size_t)r * HID + c) = o;
            }
            if (r + 8 < n) {
                float2 o = make_float2(acc[mt][nt][2] + b0, acc[mt][nt][3] + b1);
                *(float2*)(out + (size_t)(r + 8) * HID + c) = o;
            }
        }
    }
}

// ---------------------------------------------------------------------------
// PDL launch helper.
// ---------------------------------------------------------------------------
template <typename K, typename... Args>
static inline void launch_pdl(K kernel, dim3 grid, dim3 block, Args... args) {
    cudaLaunchConfig_t cfg = {};
    cfg.gridDim = grid;
    cfg.blockDim = block;
    cfg.dynamicSmemBytes = 0;
    cfg.stream = 0;
    cudaLaunchAttribute attr[1];
    attr[0].id = cudaLaunchAttributeProgrammaticStreamSerialization;
    attr[0].val.programmaticStreamSerializationAllowed = 1;
    cfg.attrs = attr;
    cfg.numAttrs = 1;
    cudaLaunchKernelEx(&cfg, kernel, args...);
}

// ---------------------------------------------------------------------------
extern "C" void kernel_launch(void* const* d_in, const int* in_sizes, int n_in,
                              void* d_out, int out_size)
{
    const float* feat = (const float*)d_in[0];
    const void*  ei   = d_in[1];
    const float* Wl   = (const float*)d_in[2];
    const float* bl   = (const float*)d_in[3];
    const float* Wr   = (const float*)d_in[4];
    float* out = (float*)d_out;

    int n = in_sizes[0] / HID;          // 20000
    int E = in_sizes[1] / 2;            // 640000
    int tot4 = n * HID / 4;

    int eb2 = (E / 2 + 255) / 256;

    launch_pdl(hist_conv_kernel, dim3(eb2), dim3(256), ei, E, feat, tot4);
    launch_pdl(scan_kernel, dim3(1), dim3(1024), n);
    launch_pdl(place_kernel, dim3(eb2), dim3(256), ei, E);
    launch_pdl(agg_kernel, dim3((n * 32 + 255) / 256), dim3(256), n);
    launch_pdl(gemm_tc, dim3((n + BM - 1) / BM), dim3(256),
               feat, Wl, bl, Wr, out, n);
}

// round 14
// speedup vs baseline: 1.3018x; 1.0594x over previous
#include <cuda_runtime.h>
#include <cuda_fp16.h>

#define HID 128
#define NMAX 20000
#define EMAX 640000

// ---- scratch (__device__ globals; allocation-free rule) ----
// g_cnt: zero at module load; scan re-zeros after reading (self-cleaning).
__device__ __align__(16) int g_cnt[NMAX];
__device__ __align__(16) int g_prefix[NMAX + 4];
__device__ int    g_rank[EMAX];
__device__ int    g_srcs[EMAX];
__device__ __half g_feat16[NMAX * HID];   // fp16 features (gather input)
__device__ __half g_agg16[NMAX * HID];    // fp16 aggregated means

// ---------------------------------------------------------------------------
// Local dtype probe: int64 node indices (<2^31) have all-zero high words.
// ---------------------------------------------------------------------------
__device__ __forceinline__ int probe_is64(const unsigned* __restrict__ w) {
    int bad = 0;
#pragma unroll
    for (int i = 0; i < 8; i++) bad |= (w[2 * i + 1] != 0u);
    return !bad;
}

// ---------------------------------------------------------------------------
// Kernel 1: PRE-SYNC: fp16 conversion + dst loads (inputs only).
// POST-SYNC: histogram + rank.
// ---------------------------------------------------------------------------
__global__ void __launch_bounds__(256) hist_conv_kernel(
    const void* __restrict__ ei, int E,
    const float* __restrict__ feat, int tot4)
{
    int gtid = blockIdx.x * blockDim.x + threadIdx.x;
    int gstride = gridDim.x * blockDim.x;

    const float4* f4 = (const float4*)feat;
    uint2* h4 = (uint2*)g_feat16;
    for (int k = gtid; k < tot4; k += gstride) {
        float4 v = f4[k];
        __half2 h0 = __floats2half2_rn(v.x, v.y);
        __half2 h1 = __floats2half2_rn(v.z, v.w);
        uint2 o;
        o.x = *(unsigned*)&h0;
        o.y = *(unsigned*)&h1;
        h4[k] = o;
    }

    int is64 = probe_is64((const unsigned*)ei);

    int base = gtid * 2;
    int m = (base < E) ? min(2, E - base) : 0;
    int d[2];
    if (m) {
        if (is64) {
            const long long* p = (const long long*)ei + E;
#pragma unroll
            for (int i = 0; i < 2; i++) if (i < m) d[i] = (int)p[base + i];
        } else {
            const int* p = (const int*)ei + E;
#pragma unroll
            for (int i = 0; i < 2; i++) if (i < m) d[i] = p[base + i];
        }
    }

    cudaGridDependencySynchronize();   // g_cnt zeroed by prev replay's scan

    if (!m) return;
    int r[2];
#pragma unroll
    for (int i = 0; i < 2; i++) if (i < m) r[i] = atomicAdd(&g_cnt[d[i]], 1);
#pragma unroll
    for (int i = 0; i < 2; i++) if (i < m) g_rank[base + i] = r[i];
}

// ---------------------------------------------------------------------------
// Kernel 2: single-block scan (register-cached, int4); re-zeros g_cnt.
// ---------------------------------------------------------------------------
#define SCH 20

__global__ void __launch_bounds__(1024) scan_kernel(int n) {
    cudaGridDependencySynchronize();
    __shared__ int warp_sums[32];
    int t = threadIdx.x;
    int lane = t & 31, wid = t >> 5;
    int beg = t * SCH;

    int c[SCH];
    int s = 0;
    bool full = (beg + SCH <= n);
    if (full) {
        const int4* p = (const int4*)(g_cnt + beg);
#pragma unroll
        for (int q = 0; q < SCH / 4; q++) {
            int4 v = p[q];
            c[q * 4 + 0] = v.x; c[q * 4 + 1] = v.y;
            c[q * 4 + 2] = v.z; c[q * 4 + 3] = v.w;
            s += v.x + v.y + v.z + v.w;
        }
        int4 z = make_int4(0, 0, 0, 0);
        int4* pz = (int4*)(g_cnt + beg);
#pragma unroll
        for (int q = 0; q < SCH / 4; q++) pz[q] = z;
    } else {
#pragma unroll
        for (int q = 0; q < SCH; q++) {
            int idx = beg + q;
            c[q] = (idx < n) ? g_cnt[idx] : 0;
            if (idx < n) g_cnt[idx] = 0;
            s += c[q];
        }
    }

    int v = s;
#pragma unroll
    for (int o = 1; o < 32; o <<= 1) {
        int u = __shfl_up_sync(0xffffffffu, v, o);
        if (lane >= o) v += u;
    }
    if (lane == 31) warp_sums[wid] = v;
    __syncthreads();
    if (wid == 0) {
        int w = warp_sums[lane];
#pragma unroll
        for (int o = 1; o < 32; o <<= 1) {
            int u = __shfl_up_sync(0xffffffffu, w, o);
            if (lane >= o) w += u;
        }
        warp_sums[lane] = w;
    }
    __syncthreads();

    int run = v - s + (wid > 0 ? warp_sums[wid - 1] : 0);
    int pre[SCH];
#pragma unroll
    for (int q = 0; q < SCH; q++) { pre[q] = run; run += c[q]; }

    if (full) {
        int4* p = (int4*)(g_prefix + beg);
#pragma unroll
        for (int q = 0; q < SCH / 4; q++)
            p[q] = make_int4(pre[q * 4 + 0], pre[q * 4 + 1],
                             pre[q * 4 + 2], pre[q * 4 + 3]);
    } else {
#pragma unroll
        for (int q = 0; q < SCH; q++)
            if (beg + q < n) g_prefix[beg + q] = pre[q];
    }
    if (t == 0) g_prefix[n] = warp_sums[31];
}

// ---------------------------------------------------------------------------
// Kernel 3: PRE-SYNC: coalesced edge loads. POST-SYNC: scatter.
// ---------------------------------------------------------------------------
__global__ void __launch_bounds__(256) place_kernel(const void* __restrict__ ei, int E) {
    int is64 = probe_is64((const unsigned*)ei);
    int base = (blockIdx.x * blockDim.x + threadIdx.x) * 2;
    int m = (base < E) ? min(2, E - base) : 0;
    int s[2], d[2];
    if (m) {
        if (is64) {
            const long long* p = (const long long*)ei;
#pragma unroll
            for (int i = 0; i < 2; i++) if (i < m) { s[i] = (int)p[base + i]; d[i] = (int)p[E + base + i]; }
        } else {
            const int* p = (const int*)ei;
#pragma unroll
            for (int i = 0; i < 2; i++) if (i < m) { s[i] = p[base + i]; d[i] = p[E + base + i]; }
        }
    }
    cudaGridDependencySynchronize();
    if (!m) return;
    int r[2], pf[2];
#pragma unroll
    for (int i = 0; i < 2; i++) if (i < m) r[i] = g_rank[base + i];
#pragma unroll
    for (int i = 0; i < 2; i++) if (i < m) pf[i] = g_prefix[d[i]];
#pragma unroll
    for (int i = 0; i < 2; i++) if (i < m) g_srcs[pf[i] + r[i]] = s[i];
}

// ---------------------------------------------------------------------------
// Kernel 4: one warp per dst node. Instruction-lean gather:
// 32-bit index math + depth-1 pairwise HADD2 before fp32 accumulate.
// ---------------------------------------------------------------------------
__global__ void __launch_bounds__(256) agg_kernel(int n) {
    cudaGridDependencySynchronize();
    int node = (blockIdx.x * blockDim.x + threadIdx.x) >> 5;
    unsigned lane = threadIdx.x & 31;
    if (node >= n) return;
    int beg = g_prefix[node], end = g_prefix[node + 1];

    const uint2* f16 = (const uint2*)g_feat16;

    float4 a0 = make_float4(0.f, 0.f, 0.f, 0.f);
    float4 a1 = a0;

    int e = beg;
    for (; e + 4 <= end; e += 4) {
        unsigned s0 = (unsigned)g_srcs[e + 0] * 32u + lane;
        unsigned s1 = (unsigned)g_srcs[e + 1] * 32u + lane;
        unsigned s2 = (unsigned)g_srcs[e + 2] * 32u + lane;
        unsigned s3 = (unsigned)g_srcs[e + 3] * 32u + lane;
        uint2 v0 = f16[s0];
        uint2 v1 = f16[s1];
        uint2 v2 = f16[s2];
        uint2 v3 = f16[s3];
        // pairwise fp16 combine (error ~2^-11, negligible)
        __half2 p0x = __hadd2(*(__half2*)&v0.x, *(__half2*)&v1.x);
        __half2 p0y = __hadd2(*(__half2*)&v0.y, *(__half2*)&v1.y);
        __half2 p1x = __hadd2(*(__half2*)&v2.x, *(__half2*)&v3.x);
        __half2 p1y = __hadd2(*(__half2*)&v2.y, *(__half2*)&v3.y);
        float2 f0x = __half22float2(p0x);
        float2 f0y = __half22float2(p0y);
        float2 f1x = __half22float2(p1x);
        float2 f1y = __half22float2(p1y);
        a0.x += f0x.x; a0.y += f0x.y; a0.z += f0y.x; a0.w += f0y.y;
        a1.x += f1x.x; a1.y += f1x.y; a1.z += f1y.x; a1.w += f1y.y;
    }
    if (e + 2 <= end) {
        unsigned s0 = (unsigned)g_srcs[e + 0] * 32u + lane;
        unsigned s1 = (unsigned)g_srcs[e + 1] * 32u + lane;
        uint2 v0 = f16[s0];
        uint2 v1 = f16[s1];
        __half2 px = __hadd2(*(__half2*)&v0.x, *(__half2*)&v1.x);
        __half2 py = __hadd2(*(__half2*)&v0.y, *(__half2*)&v1.y);
        float2 fx = __half22float2(px);
        float2 fy = __half22float2(py);
        a0.x += fx.x; a0.y += fx.y; a0.z += fy.x; a0.w += fy.y;
        e += 2;
    }
    if (e < end) {
        unsigned s0 = (unsigned)g_srcs[e] * 32u + lane;
        uint2 v = f16[s0];
        float2 fx = __half22float2(*(__half2*)&v.x);
        float2 fy = __half22float2(*(__half2*)&v.y);
        a0.x += fx.x; a0.y += fx.y; a0.z += fy.x; a0.w += fy.y;
    }
    float inv = (end > beg) ? 1.f / (float)(end - beg) : 0.f;
    float sx = (a0.x + a1.x) * inv;
    float sy = (a0.y + a1.y) * inv;
    float sz = (a0.z + a1.z) * inv;
    float sw = (a0.w + a1.w) * inv;
    __half2 o0 = __floats2half2_rn(sx, sy);
    __half2 o1 = __floats2half2_rn(sz, sw);
    uint2 st;
    st.x = *(unsigned*)&o0;
    st.y = *(unsigned*)&o1;
    ((uint2*)g_agg16)[(unsigned)node * 32u + lane] = st;
}

// ---------------------------------------------------------------------------
// Kernel 5: TF32 GEMM. PRE-SYNC: feat@Wr chunks 8..15 overlap agg;
// POST-SYNC: agg16@Wl chunks 0..7.
// ---------------------------------------------------------------------------
#define BM 64
#define BK 16
#define SW(r, c) ((r) * BK + ((c) ^ ((((r) >> 1) & 3) << 2)))

__device__ __forceinline__ unsigned f2tf32(float x) {
    unsigned r;
    asm("cvt.rna.tf32.f32 %0, %1;" : "=r"(r) : "f"(x));
    return r;
}

__device__ __forceinline__ void mma_tf32(float* c, const unsigned* a, const unsigned* b) {
    asm volatile(
        "mma.sync.aligned.m16n8k8.row.col.f32.tf32.tf32.f32 "
        "{%0,%1,%2,%3},{%4,%5,%6,%7},{%8,%9},{%0,%1,%2,%3};"
        : "+f"(c[0]), "+f"(c[1]), "+f"(c[2]), "+f"(c[3])
        : "r"(a[0]), "r"(a[1]), "r"(a[2]), "r"(a[3]), "r"(b[0]), "r"(b[1]));
}

__global__ void __launch_bounds__(256) gemm_tc(
    const float* __restrict__ feat,
    const float* __restrict__ Wl,
    const float* __restrict__ bl,
    const float* __restrict__ Wr,
    float* __restrict__ out,
    int n)
{
    __shared__ unsigned sA[2][BM * BK];
    __shared__ unsigned sB[2][128 * BK];

    int tid = threadIdx.x;
    int wid = tid >> 5, lane = tid & 31;
    int wm = wid & 1;
    int wn = wid >> 1;
    int g = lane >> 2;
    int tg = lane & 3;
    int row0 = blockIdx.x * BM;

    float acc[2][4][4];
#pragma unroll
    for (int mt = 0; mt < 2; mt++)
#pragma unroll
        for (int nt = 0; nt < 4; nt++)
#pragma unroll
            for (int q = 0; q < 4; q++) acc[mt][nt][q] = 0.f;

    uint4 rga, rgb[2];

    auto ldg_chunk = [&](int ck) {
        int k0 = (ck & 7) * BK;
        int r = tid >> 2;
        int c4 = (tid & 3) * 4;
        int gr = row0 + r;
        if (ck < 8) {
            float2 f0 = make_float2(0.f, 0.f), f1 = f0;
            if (gr < n) {
                uint2 hv = ((const uint2*)g_agg16)[((size_t)gr * HID + k0 + c4) >> 2];
                f0 = __half22float2(*(__half2*)&hv.x);
                f1 = __half22float2(*(__half2*)&hv.y);
            }
            rga = make_uint4(f2tf32(f0.x), f2tf32(f0.y), f2tf32(f1.x), f2tf32(f1.y));
        } else {
            float4 v = make_float4(0.f, 0.f, 0.f, 0.f);
            if (gr < n) v = *(const float4*)(feat + (size_t)gr * HID + k0 + c4);
            rga = make_uint4(f2tf32(v.x), f2tf32(v.y), f2tf32(v.z), f2tf32(v.w));
        }
        const float* W = (ck < 8) ? Wl : Wr;
#pragma unroll
        for (int q = 0; q < 2; q++) {
            int idx = q * 256 + tid;
            int br = idx >> 2;
            int bc4 = (idx & 3) * 4;
            float4 w = *(const float4*)(W + (size_t)br * HID + k0 + bc4);
            rgb[q] = make_uint4(f2tf32(w.x), f2tf32(w.y), f2tf32(w.z), f2tf32(w.w));
        }
    };

    auto sts_chunk = [&](int b) {
        int r = tid >> 2;
        int c4 = (tid & 3) * 4;
        *(uint4*)&sA[b][SW(r, c4)] = rga;
#pragma unroll
        for (int q = 0; q < 2; q++) {
            int idx = q * 256 + tid;
            int br = idx >> 2;
            int bc4 = (idx & 3) * 4;
            *(uint4*)&sB[b][SW(br, bc4)] = rgb[q];
        }
    };

    ldg_chunk(8);
    sts_chunk(0);
    __syncthreads();

    for (int i = 0; i < 16; i++) {
        if (i < 15) {
            int nxt = (i + 9) & 15;
            if (nxt == 0) cudaGridDependencySynchronize();
            ldg_chunk(nxt);
        }
        int b = i & 1;
#pragma unroll
        for (int kk = 0; kk < 2; kk++) {
            int ko = kk * 8;
            unsigned af[2][4], bf[4][2];
#pragma unroll
            for (int mt = 0; mt < 2; mt++) {
                int rb_ = wm * 32 + mt * 16;
                af[mt][0] = sA[b][SW(rb_ + g,     ko + tg)];
                af[mt][1] = sA[b][SW(rb_ + g + 8, ko + tg)];
                af[mt][2] = sA[b][SW(rb_ + g,     ko + tg + 4)];
                af[mt][3] = sA[b][SW(rb_ + g + 8, ko + tg + 4)];
            }
#pragma unroll
            for (int nt = 0; nt < 4; nt++) {
                int cb = wn * 32 + nt * 8;
                bf[nt][0] = sB[b][SW(cb + g, ko + tg)];
                bf[nt][1] = sB[b][SW(cb + g, ko + tg + 4)];
            }
#pragma unroll
            for (int mt = 0; mt < 2; mt++)
#pragma unroll
                for (int nt = 0; nt < 4; nt++)
                    mma_tf32(acc[mt][nt], af[mt], bf[nt]);
        }
        if (i < 15) {
            sts_chunk((i + 1) & 1);
            __syncthreads();
        }
    }

#pragma unroll
    for (int nt = 0; nt < 4; nt++) {
        int c = wn * 32 + nt * 8 + tg * 2;
        float b0 = bl[c], b1 = bl[c + 1];
#pragma unroll
        for (int mt = 0; mt < 2; mt++) {
            int r = row0 + wm * 32 + mt * 16 + g;
            if (r < n) {
                float2 o = make_float2(acc[mt][nt][0] + b0, acc[mt][nt][1] + b1);
                *(float2*)(out + (size_t)r * HID + c) = o;
            }
            if (r + 8 < n) {
                float2 o = make_float2(acc[mt][nt][2] + b0, acc[mt][nt][3] + b1);
                *(float2*)(out + (size_t)(r + 8) * HID + c) = o;
            }
        }
    }
}

// ---------------------------------------------------------------------------
// PDL launch helper.
// ---------------------------------------------------------------------------
template <typename K, typename... Args>
static inline void launch_pdl(K kernel, dim3 grid, dim3 block, Args... args) {
    cudaLaunchConfig_t cfg = {};
    cfg.gridDim = grid;
    cfg.blockDim = block;
    cfg.dynamicSmemBytes = 0;
    cfg.stream = 0;
    cudaLaunchAttribute attr[1];
    attr[0].id = cudaLaunchAttributeProgrammaticStreamSerialization;
    attr[0].val.programmaticStreamSerializationAllowed = 1;
    cfg.attrs = attr;
    cfg.numAttrs = 1;
    cudaLaunchKernelEx(&cfg, kernel, args...);
}

// ---------------------------------------------------------------------------
extern "C" void kernel_launch(void* const* d_in, const int* in_sizes, int n_in,
                              void* d_out, int out_size)
{
    const float* feat = (const float*)d_in[0];
    const void*  ei   = d_in[1];
    const float* Wl   = (const float*)d_in[2];
    const float* bl   = (const float*)d_in[3];
    const float* Wr   = (const float*)d_in[4];
    float* out = (float*)d_out;

    int n = in_sizes[0] / HID;          // 20000
    int E = in_sizes[1] / 2;            // 640000
    int tot4 = n * HID / 4;

    int eb2 = (E / 2 + 255) / 256;

    launch_pdl(hist_conv_kernel, dim3(eb2), dim3(256), ei, E, feat, tot4);
    launch_pdl(scan_kernel, dim3(1), dim3(1024), n);
    launch_pdl(place_kernel, dim3(eb2), dim3(256), ei, E);
    launch_pdl(agg_kernel, dim3((n * 32 + 255) / 256), dim3(256), n);
    launch_pdl(gemm_tc, dim3((n + BM - 1) / BM), dim3(256),
               feat, Wl, bl, Wr, out, n);
}